// round 14
// baseline (speedup 1.0000x reference)
#include <cuda_runtime.h>
#include <cstdint>

#define TPB 512

#define NBATCH 2048
#define CDIM 192
#define NPOS 64
#define NHEAD 6
#define NGRP 3
#define NS 16

#define RSX 68     // row stride for x / attn-out tile [192][64]
#define RSQ 68     // row stride for q tile [192][64]
#define RSW 68     // row stride for weight pass buffer rows [192 rows][64 k +4 pad]
#define RSS 16     // row stride for samp/k/v tiles [192][16]
#define WBUF 13056 // floats per weight pass buffer (192*68)

// shared-memory layout (float offsets)
#define O_XS    0          // 13056 (x; later attn-out)
#define O_QS    13056      // 13056
#define O_WT    26112      // UNION: 2 weight pass buffers (2*13056)  OR  samp/k/v
#define O_SAMP  (O_WT)             // 3072 (buffer0 region)
#define O_KS    (O_WT + 3072)      // 3072
#define O_VS    (O_WT + 6144)      // 3072
// persistent tail (never aliased by WT)
#define O_RPE   52224      // 1350
#define O_DWW   53574      // 576
#define O_DWB   54150      // 64
#define O_LNG   54214      // 64
#define O_LNB   54278      // 64
#define O_PWW   54342      // 128
#define O_POS   54470      // 96
#define O_SMPW  54566      // 192
#define O_SMPI  54758      // 192 (ints)
#define SMEMF   54950
#define SMEM_BYTES (SMEMF * 4)   // 219800 B

#define Y_SIZE   (NBATCH * CDIM * NPOS)
#define PR_SIZE  (NBATCH * NGRP * NS * 2)
#define POS_OFF  Y_SIZE
#define REF_OFF  (Y_SIZE + PR_SIZE)

typedef unsigned long long ull;

__device__ __forceinline__ ull ffma2(ull a, ull b, ull c) {
    ull d;
    asm("fma.rn.f32x2 %0, %1, %2, %3;" : "=l"(d) : "l"(a), "l"(b), "l"(c));
    return d;
}
__device__ __forceinline__ ull add2(ull a, ull b) {
    ull d;
    asm("add.rn.f32x2 %0, %1, %2;" : "=l"(d) : "l"(a), "l"(b));
    return d;
}
__device__ __forceinline__ ull pk2d(float v) {          // (v, v)
    ull r;
    asm("mov.b64 %0, {%1, %1};" : "=l"(r) : "f"(v));
    return r;
}
__device__ __forceinline__ void unpk2(float& lo, float& hi, ull v) {
    asm("mov.b64 {%0, %1}, %2;" : "=f"(lo), "=f"(hi) : "l"(v));
}

// ---- async-stage one 64-k pass of weights ----
// Row permutation: co -> idx = (co%6)*32 + co/6, so a warp's 6-co read group
// (co = 6cb+i, i fixed per LDS) maps to rows i*32+cb: bank offsets 4*cb mod 32,
// conflict-free within the 4-cycle LDS.128 delivery floor.
__device__ __forceinline__ void cp_stage(const float* __restrict__ W, int k0,
                                         uint32_t dstBase, int tid)
{
#pragma unroll
    for (int j = 0; j < 6; ++j) {
        int q = tid + j * 512;
        int co = q >> 4;
        int kc = q & 15;
        int idx = (co % 6) * 32 + co / 6;
        uint32_t dst = dstBase + (uint32_t)(idx * RSW + kc * 4) * 4u;
        const float* src = W + co * 192 + k0 + kc * 4;
        asm volatile("cp.async.cg.shared.global [%0], [%1], 16;" :: "r"(dst), "l"(src));
    }
    asm volatile("cp.async.commit_group;" ::: "memory");
}

// 192x64 GEMM, K=192: out[co][p] = bias[co] + sum_k W[co][k] * in[k][p]
// K split across lane pairs (lane bit 4): each lane computes a 6co x 8p tile
// over 96 k (1.17 B/MAC), then combines via shfl.xor(16) + add.f32x2.
// 3 K-passes of 64 staged via cp.async double buffer.
template <bool TO_SMEM>
__device__ __forceinline__ void gemm_big(const float* __restrict__ W, const float* __restrict__ bias,
                                         int inOff, float* __restrict__ gout,
                                         float* __restrict__ sm, uint32_t sb, int tid)
{
    const int warp = tid >> 5, lane = tid & 31;
    const int khalf = lane >> 4;                  // 0/1: k-half within each 64-chunk
    const int cb = (lane & 15) + (warp & 1) * 16; // 0..31 co-blocks (of 6)
    const int pb = warp >> 1;                     // 0..7 p-blocks (of 8)
    const int col = cb * 6;
    const int p = pb * 8;
    const int kq0 = khalf * 32;

    ull acc[6][4];                                 // [co][p-pair], bias added post-combine
#pragma unroll
    for (int i = 0; i < 6; ++i)
#pragma unroll
        for (int j = 0; j < 4; ++j) acc[i][j] = 0ULL;

    const uint32_t xbase = sb + (uint32_t)(inOff + p) * 4u;

#pragma unroll 1
    for (int pass = 0; pass < 3; ++pass) {
        if (pass < 2) {
            cp_stage(W, (pass + 1) * 64, sb + (uint32_t)(O_WT + (pass & 1) * WBUF) * 4u, tid);
            asm volatile("cp.async.wait_group 1;" ::: "memory");
        } else {
            asm volatile("cp.async.wait_group 0;" ::: "memory");
        }
        __syncthreads();
        const int wb = O_WT + ((pass + 1) & 1) * WBUF;
        const int kb = pass * 64;
        const float* wrow = &sm[wb + cb * RSW + kq0];
        const uint32_t xk = xbase + (uint32_t)((kb + kq0) * RSX) * 4u;
#pragma unroll 1
        for (int k4 = 0; k4 < 8; ++k4) {
            float4 wv0 = *(const float4*)&wrow[0 * 32 * RSW + k4 * 4];
            float4 wv1 = *(const float4*)&wrow[1 * 32 * RSW + k4 * 4];
            float4 wv2 = *(const float4*)&wrow[2 * 32 * RSW + k4 * 4];
            float4 wv3 = *(const float4*)&wrow[3 * 32 * RSW + k4 * 4];
            float4 wv4 = *(const float4*)&wrow[4 * 32 * RSW + k4 * 4];
            float4 wv5 = *(const float4*)&wrow[5 * 32 * RSW + k4 * 4];
#pragma unroll
            for (int j = 0; j < 4; ++j) {
                ull x01, x23, x45, x67;
                uint32_t xa = xk + (uint32_t)((k4 * 4 + j) * RSX) * 4u;
                asm("ld.shared.v2.b64 {%0,%1}, [%2];" : "=l"(x01), "=l"(x23) : "r"(xa));
                asm("ld.shared.v2.b64 {%0,%1}, [%2+16];" : "=l"(x45), "=l"(x67) : "r"(xa));
                float w0 = (j == 0) ? wv0.x : (j == 1) ? wv0.y : (j == 2) ? wv0.z : wv0.w;
                float w1 = (j == 0) ? wv1.x : (j == 1) ? wv1.y : (j == 2) ? wv1.z : wv1.w;
                float w2 = (j == 0) ? wv2.x : (j == 1) ? wv2.y : (j == 2) ? wv2.z : wv2.w;
                float w3 = (j == 0) ? wv3.x : (j == 1) ? wv3.y : (j == 2) ? wv3.z : wv3.w;
                float w4 = (j == 0) ? wv4.x : (j == 1) ? wv4.y : (j == 2) ? wv4.z : wv4.w;
                float w5 = (j == 0) ? wv5.x : (j == 1) ? wv5.y : (j == 2) ? wv5.z : wv5.w;
                ull d;
                d = pk2d(w0); acc[0][0] = ffma2(d, x01, acc[0][0]); acc[0][1] = ffma2(d, x23, acc[0][1]);
                              acc[0][2] = ffma2(d, x45, acc[0][2]); acc[0][3] = ffma2(d, x67, acc[0][3]);
                d = pk2d(w1); acc[1][0] = ffma2(d, x01, acc[1][0]); acc[1][1] = ffma2(d, x23, acc[1][1]);
                              acc[1][2] = ffma2(d, x45, acc[1][2]); acc[1][3] = ffma2(d, x67, acc[1][3]);
                d = pk2d(w2); acc[2][0] = ffma2(d, x01, acc[2][0]); acc[2][1] = ffma2(d, x23, acc[2][1]);
                              acc[2][2] = ffma2(d, x45, acc[2][2]); acc[2][3] = ffma2(d, x67, acc[2][3]);
                d = pk2d(w3); acc[3][0] = ffma2(d, x01, acc[3][0]); acc[3][1] = ffma2(d, x23, acc[3][1]);
                              acc[3][2] = ffma2(d, x45, acc[3][2]); acc[3][3] = ffma2(d, x67, acc[3][3]);
                d = pk2d(w4); acc[4][0] = ffma2(d, x01, acc[4][0]); acc[4][1] = ffma2(d, x23, acc[4][1]);
                              acc[4][2] = ffma2(d, x45, acc[4][2]); acc[4][3] = ffma2(d, x67, acc[4][3]);
                d = pk2d(w5); acc[5][0] = ffma2(d, x01, acc[5][0]); acc[5][1] = ffma2(d, x23, acc[5][1]);
                              acc[5][2] = ffma2(d, x45, acc[5][2]); acc[5][3] = ffma2(d, x67, acc[5][3]);
            }
        }
        __syncthreads();   // buffer free for the next pass's cp.async
    }

    // combine k-halves across lane pairs
#pragma unroll
    for (int i = 0; i < 6; ++i)
#pragma unroll
        for (int j = 0; j < 4; ++j) {
            ull o = __shfl_xor_sync(0xffffffffu, acc[i][j], 16);
            acc[i][j] = add2(acc[i][j], o);
        }

    // each lane writes its half of the 8 p's (khalf 0 -> p..p+3, khalf 1 -> p+4..p+7)
    const int pw = p + khalf * 4;
    const int jb = khalf * 2;
#pragma unroll
    for (int i = 0; i < 6; ++i) {
        float bi = bias[col + i];
        float4 v;
        unpk2(v.x, v.y, acc[i][jb]);
        unpk2(v.z, v.w, acc[i][jb + 1]);
        v.x += bi; v.y += bi; v.z += bi; v.w += bi;
        if (TO_SMEM) *(float4*)&sm[O_QS + (col + i) * RSQ + pw] = v;
        else         *(float4*)&gout[(col + i) * 64 + pw] = v;
    }
    __syncthreads();
}

__global__ void __launch_bounds__(TPB, 1)
dat_fused_kernel(const float* __restrict__ x,
                 const float* __restrict__ wq, const float* __restrict__ bq,
                 const float* __restrict__ wk, const float* __restrict__ bk,
                 const float* __restrict__ wv, const float* __restrict__ bv,
                 const float* __restrict__ wo, const float* __restrict__ bo,
                 const float* __restrict__ dww, const float* __restrict__ dwb,
                 const float* __restrict__ lng, const float* __restrict__ lnb,
                 const float* __restrict__ pww, const float* __restrict__ rpe,
                 float* __restrict__ out, int writePR)
{
    extern __shared__ float sm[];
    const int b = blockIdx.x;
    const int tid = threadIdx.x;
    const uint32_t sb = (uint32_t)__cvta_generic_to_shared(sm);

    // async-prefetch q-proj weight pass 0 into buffer 1 (overlaps x staging)
    cp_stage(wq, 0, sb + (uint32_t)(O_WT + WBUF) * 4u, tid);

    // ---- stage x (transpose to [c][p]) and persistent params ----
    const float* xb = x + (size_t)b * (NPOS * CDIM);
    for (int t = tid; t < NPOS * CDIM; t += TPB) {
        int p = t / CDIM;
        int c = t - p * CDIM;
        sm[O_XS + c * RSX + p] = xb[t];
    }
    for (int t = tid; t < 1350; t += TPB) sm[O_RPE + t] = rpe[t];
    for (int t = tid; t < 576; t += TPB) sm[O_DWW + t] = dww[t];
    if (tid < 64) {
        sm[O_DWB + tid] = dwb[tid];
        sm[O_LNG + tid] = lng[tid];
        sm[O_LNB + tid] = lnb[tid];
    }
    if (tid >= 64 && tid < 192) sm[O_PWW + tid - 64] = pww[tid - 64];
    __syncthreads();

    // ---- q = Wq x + bq ----
    gemm_big<true>(wq, bq, O_XS, nullptr, sm, sb, tid);

    // ---- offset network: 48 items (group g, sample s), 3 per warp ----
    const int warp = tid >> 5, lane = tid & 31;
    for (int kk = 0; kk < 3; ++kk) {
        const int item = warp * 3 + kk;
        const int g = item >> 4;
        const int s = item & 15;
        const int si = s >> 2, sj = s & 3;
        const int ch0 = lane, ch1 = lane + 32;
        float v0 = sm[O_DWB + ch0];
        float v1 = sm[O_DWB + ch1];
        const int iy0 = 2 * si - 1, ix0 = 2 * sj - 1;
#pragma unroll
        for (int di = 0; di < 3; ++di) {
            int iy = iy0 + di;
            if (iy < 0 || iy > 7) continue;
#pragma unroll
            for (int dj = 0; dj < 3; ++dj) {
                int ix = ix0 + dj;
                if (ix < 0 || ix > 7) continue;
                float q0 = sm[O_QS + (g * 64 + ch0) * RSQ + iy * 8 + ix];
                float q1 = sm[O_QS + (g * 64 + ch1) * RSQ + iy * 8 + ix];
                v0 += sm[O_DWW + ch0 * 9 + di * 3 + dj] * q0;
                v1 += sm[O_DWW + ch1 * 9 + di * 3 + dj] * q1;
            }
        }
        float ssum = v0 + v1, ssq = v0 * v0 + v1 * v1;
#pragma unroll
        for (int o = 16; o > 0; o >>= 1) {
            ssum += __shfl_xor_sync(0xffffffffu, ssum, o);
            ssq += __shfl_xor_sync(0xffffffffu, ssq, o);
        }
        float mu = ssum * (1.0f / 64.0f);
        float var = ssq * (1.0f / 64.0f) - mu * mu;
        float rstd = rsqrtf(var + 1e-5f);
        v0 = (v0 - mu) * rstd * sm[O_LNG + ch0] + sm[O_LNB + ch0];
        v1 = (v1 - mu) * rstd * sm[O_LNG + ch1] + sm[O_LNB + ch1];
        v0 = 0.5f * v0 * (1.0f + erff(v0 * 0.70710678118654752f));
        v1 = 0.5f * v1 * (1.0f + erff(v1 * 0.70710678118654752f));
        float o0 = sm[O_PWW + ch0] * v0 + sm[O_PWW + ch1] * v1;
        float o1 = sm[O_PWW + 64 + ch0] * v0 + sm[O_PWW + 64 + ch1] * v1;
#pragma unroll
        for (int o = 16; o > 0; o >>= 1) {
            o0 += __shfl_xor_sync(0xffffffffu, o0, o);
            o1 += __shfl_xor_sync(0xffffffffu, o1, o);
        }
        if (lane == 0) {
            float offy = tanhf(o0) * (2.0f / 3.0f);
            float offx = tanhf(o1) * (2.0f / 3.0f);
            float ry = (2 * si - 3) * 0.25f;
            float rx = (2 * sj - 3) * 0.25f;
            float py = offy + ry;
            float px = offx + rx;
            sm[O_POS + item * 2 + 0] = py;
            sm[O_POS + item * 2 + 1] = px;
            float gx = (px + 1.0f) * 3.5f;
            float gy = (py + 1.0f) * 3.5f;
            float x0f = floorf(gx), y0f = floorf(gy);
            int jx0 = (int)x0f, jy0 = (int)y0f;
            float wx1 = gx - x0f, wy1 = gy - y0f;
            float wxs[2] = {1.0f - wx1, wx1};
            float wys[2] = {1.0f - wy1, wy1};
            int* smpI = (int*)sm;
#pragma unroll
            for (int n = 0; n < 4; ++n) {
                int xi = jx0 + (n & 1);
                int yi = jy0 + (n >> 1);
                bool val = (xi >= 0 && xi <= 7 && yi >= 0 && yi <= 7);
                sm[O_SMPW + item * 4 + n] = val ? wxs[n & 1] * wys[n >> 1] : 0.0f;
                smpI[O_SMPI + item * 4 + n] = val ? (yi * 8 + xi) : 0;
            }
            if (writePR) {
                size_t po = ((size_t)b * 48 + item) * 2;
                out[POS_OFF + po + 0] = py;
                out[POS_OFF + po + 1] = px;
                out[REF_OFF + po + 0] = ry;
                out[REF_OFF + po + 1] = rx;
            }
        }
    }
    __syncthreads();

    // ---- bilinear sample x at pos -> samp[c][s] ----
    for (int t = tid; t < CDIM * NS; t += TPB) {
        int c = t >> 4;
        int s = t & 15;
        int item = (c >> 6) * 16 + s;
        const float* wp = &sm[O_SMPW + item * 4];
        const int* ip = ((const int*)sm) + O_SMPI + item * 4;
        const float* row = &sm[O_XS + c * RSX];
        sm[O_SAMP + c * RSS + s] =
            wp[0] * row[ip[0]] + wp[1] * row[ip[1]] + wp[2] * row[ip[2]] + wp[3] * row[ip[3]];
    }
    __syncthreads();

    // ---- k, v projections: weights direct from L2, thread = (co, 8 s-cols) ----
    if (tid < 384) {
        const int co = tid >> 1;
        const int sh = (tid & 1) * 8;
        const float bkc = bk[co], bvc = bv[co];
        float4 ak0 = make_float4(bkc, bkc, bkc, bkc), ak1 = ak0;
        float4 av0 = make_float4(bvc, bvc, bvc, bvc), av1 = av0;
#pragma unroll 4
        for (int k4 = 0; k4 < 48; ++k4) {
            float4 wk4 = __ldg((const float4*)&wk[co * 192 + k4 * 4]);
            float4 wv4 = __ldg((const float4*)&wv[co * 192 + k4 * 4]);
#pragma unroll
            for (int j = 0; j < 4; ++j) {
                float wkj = (j == 0) ? wk4.x : (j == 1) ? wk4.y : (j == 2) ? wk4.z : wk4.w;
                float wvj = (j == 0) ? wv4.x : (j == 1) ? wv4.y : (j == 2) ? wv4.z : wv4.w;
                float4 s0 = *(const float4*)&sm[O_SAMP + (k4 * 4 + j) * RSS + sh];
                float4 s1 = *(const float4*)&sm[O_SAMP + (k4 * 4 + j) * RSS + sh + 4];
                ak0.x += wkj * s0.x; ak0.y += wkj * s0.y; ak0.z += wkj * s0.z; ak0.w += wkj * s0.w;
                ak1.x += wkj * s1.x; ak1.y += wkj * s1.y; ak1.z += wkj * s1.z; ak1.w += wkj * s1.w;
                av0.x += wvj * s0.x; av0.y += wvj * s0.y; av0.z += wvj * s0.z; av0.w += wvj * s0.w;
                av1.x += wvj * s1.x; av1.y += wvj * s1.y; av1.z += wvj * s1.z; av1.w += wvj * s1.w;
            }
        }
        *(float4*)&sm[O_KS + co * RSS + sh] = ak0;
        *(float4*)&sm[O_KS + co * RSS + sh + 4] = ak1;
        *(float4*)&sm[O_VS + co * RSS + sh] = av0;
        *(float4*)&sm[O_VS + co * RSS + sh + 4] = av1;
    }
    __syncthreads();

    // async-prefetch o-proj weight pass 0 into buffer 1 (upper half — does not
    // alias SAMP/KS/VS in buffer 0); attention below hides the latency.
    cp_stage(wo, 0, sb + (uint32_t)(O_WT + WBUF) * 4u, tid);

    // ---- attention: item = (head, query position), 384 items ----
    for (int it = tid; it < NHEAD * NPOS; it += TPB) {
        const int h = it >> 6;
        const int p = it & 63;
        const int g = h >> 1;
        float a[16];
#pragma unroll
        for (int s = 0; s < 16; ++s) a[s] = 0.0f;
#pragma unroll 4
        for (int c = 0; c < 32; ++c) {
            float qv = sm[O_QS + (h * 32 + c) * RSQ + p];
            const float4* kr = (const float4*)&sm[O_KS + (h * 32 + c) * RSS];
            float4 k0 = kr[0], k1 = kr[1], k2 = kr[2], k3 = kr[3];
            a[0] += qv * k0.x; a[1] += qv * k0.y; a[2] += qv * k0.z; a[3] += qv * k0.w;
            a[4] += qv * k1.x; a[5] += qv * k1.y; a[6] += qv * k1.z; a[7] += qv * k1.w;
            a[8] += qv * k2.x; a[9] += qv * k2.y; a[10] += qv * k2.z; a[11] += qv * k2.w;
            a[12] += qv * k3.x; a[13] += qv * k3.y; a[14] += qv * k3.z; a[15] += qv * k3.w;
        }
        const float scale = 0.17677669529663687f;
        float qy = (2 * (p >> 3) - 7) * 0.125f;
        float qx = (2 * (p & 7) - 7) * 0.125f;
        const float* rpeh = &sm[O_RPE + h * 225];
        float mx = -1e30f;
#pragma unroll
        for (int s = 0; s < 16; ++s) {
            float py = sm[O_POS + (g * 16 + s) * 2 + 0];
            float px = sm[O_POS + (g * 16 + s) * 2 + 1];
            float dy = (qy - py) * 0.5f;
            float dx = (qx - px) * 0.5f;
            float gx = (dx + 1.0f) * 7.0f;
            float gy = (dy + 1.0f) * 7.0f;
            float x0f = floorf(gx), y0f = floorf(gy);
            int jx0 = (int)x0f, jy0 = (int)y0f;
            float wx1 = gx - x0f, wy1 = gy - y0f;
            float bias = 0.0f;
            if (jx0 >= 0 && jx0 <= 14 && jy0 >= 0 && jy0 <= 14)
                bias += (1.0f - wx1) * (1.0f - wy1) * rpeh[jy0 * 15 + jx0];
            if (jx0 + 1 >= 0 && jx0 + 1 <= 14 && jy0 >= 0 && jy0 <= 14)
                bias += wx1 * (1.0f - wy1) * rpeh[jy0 * 15 + jx0 + 1];
            if (jx0 >= 0 && jx0 <= 14 && jy0 + 1 >= 0 && jy0 + 1 <= 14)
                bias += (1.0f - wx1) * wy1 * rpeh[(jy0 + 1) * 15 + jx0];
            if (jx0 + 1 >= 0 && jx0 + 1 <= 14 && jy0 + 1 >= 0 && jy0 + 1 <= 14)
                bias += wx1 * wy1 * rpeh[(jy0 + 1) * 15 + jx0 + 1];
            a[s] = a[s] * scale + bias;
            mx = fmaxf(mx, a[s]);
        }
        float ssum = 0.0f;
#pragma unroll
        for (int s = 0; s < 16; ++s) { a[s] = __expf(a[s] - mx); ssum += a[s]; }
        float inv = 1.0f / ssum;
#pragma unroll
        for (int s = 0; s < 16; ++s) a[s] *= inv;
#pragma unroll 4
        for (int cl = 0; cl < 32; ++cl) {
            int c = h * 32 + cl;
            const float4* vr = (const float4*)&sm[O_VS + c * RSS];
            float4 v0 = vr[0], v1 = vr[1], v2 = vr[2], v3 = vr[3];
            float acc = a[0]*v0.x + a[1]*v0.y + a[2]*v0.z + a[3]*v0.w
                      + a[4]*v1.x + a[5]*v1.y + a[6]*v1.z + a[7]*v1.w
                      + a[8]*v2.x + a[9]*v2.y + a[10]*v2.z + a[11]*v2.w
                      + a[12]*v3.x + a[13]*v3.y + a[14]*v3.z + a[15]*v3.w;
            sm[O_XS + c * RSX + p] = acc;
        }
    }
    __syncthreads();

    // ---- y = Wo out + bo (direct to gmem) ----
    gemm_big<false>(wo, bo, O_XS, out + (size_t)b * (CDIM * NPOS), sm, sb, tid);
}

extern "C" void kernel_launch(void* const* d_in, const int* in_sizes, int n_in,
                              void* d_out, int out_size)
{
    (void)in_sizes; (void)n_in;
    const float* x   = (const float*)d_in[0];
    const float* wq  = (const float*)d_in[1];
    const float* bq  = (const float*)d_in[2];
    const float* wk  = (const float*)d_in[3];
    const float* bk  = (const float*)d_in[4];
    const float* wv  = (const float*)d_in[5];
    const float* bv  = (const float*)d_in[6];
    const float* wo  = (const float*)d_in[7];
    const float* bo  = (const float*)d_in[8];
    const float* dww = (const float*)d_in[9];
    const float* dwb = (const float*)d_in[10];
    const float* lng = (const float*)d_in[11];
    const float* lnb = (const float*)d_in[12];
    const float* pww = (const float*)d_in[13];
    const float* rpe = (const float*)d_in[14];
    float* out = (float*)d_out;

    int writePR = (out_size >= (REF_OFF + PR_SIZE)) ? 1 : 0;

    cudaFuncSetAttribute(dat_fused_kernel,
                         cudaFuncAttributeMaxDynamicSharedMemorySize, SMEM_BYTES);
    dat_fused_kernel<<<NBATCH, TPB, SMEM_BYTES>>>(
        x, wq, bq, wk, bk, wv, bv, wo, bo, dww, dwb, lng, lnb, pww, rpe, out, writePR);
}

// round 16
// speedup vs baseline: 1.6415x; 1.6415x over previous
#include <cuda_runtime.h>
#include <cstdint>

#define TPB 512

#define NBATCH 2048
#define CDIM 192
#define NPOS 64
#define NHEAD 6
#define NGRP 3
#define NS 16

#define RSXU 34    // uint32 row stride for f16 x/attn-out tile [192][32 f16x2 +2 pad]
#define RSQ 68     // row stride for q tile [192][64]
#define RSW 68     // row stride for weight pass buffer [192 co][64 k +4 pad]
#define RSS 16     // row stride for samp/k/v tiles [192][16]
#define WBUF 13056 // floats per weight pass buffer (192*68)

// shared-memory layout (float/uint 4B offsets)
#define O_XS    0          // 6528 uints: f16 x tile (later f16 attn-out)
#define O_QS    13056      // 13056
#define O_WT    26112      // UNION: 2 weight pass buffers (2*13056)  OR  samp/k/v
#define O_SAMP  (O_WT)             // 3072 (buffer0 region)
#define O_KS    (O_WT + 3072)      // 3072
#define O_VS    (O_WT + 6144)      // 3072
// persistent tail (never aliased by WT)
#define O_RPE   52224      // 1350
#define O_DWW   53574      // 576
#define O_DWB   54150      // 64
#define O_LNG   54214      // 64
#define O_LNB   54278      // 64
#define O_PWW   54342      // 128
#define O_POS   54470      // 96
#define O_SMPW  54566      // 192
#define O_SMPI  54758      // 192 (ints)
#define SMEMF   54950
#define SMEM_BYTES (SMEMF * 4)   // 219800 B

#define Y_SIZE   (NBATCH * CDIM * NPOS)
#define PR_SIZE  (NBATCH * NGRP * NS * 2)
#define POS_OFF  Y_SIZE
#define REF_OFF  (Y_SIZE + PR_SIZE)

typedef unsigned long long ull;

__device__ __forceinline__ ull ffma2(ull a, ull b, ull c) {
    ull d;
    asm("fma.rn.f32x2 %0, %1, %2, %3;" : "=l"(d) : "l"(a), "l"(b), "l"(c));
    return d;
}
__device__ __forceinline__ ull pk2d(float v) {          // (v, v)
    ull r;
    asm("mov.b64 %0, {%1, %1};" : "=l"(r) : "f"(v));
    return r;
}
__device__ __forceinline__ ull pk2(float lo, float hi) {
    ull r;
    asm("mov.b64 %0, {%1, %2};" : "=l"(r) : "f"(lo), "f"(hi));
    return r;
}
__device__ __forceinline__ void unpk2(float& lo, float& hi, ull v) {
    asm("mov.b64 {%0, %1}, %2;" : "=f"(lo), "=f"(hi) : "l"(v));
}
// packed uint32 of 2 f16 -> f32x2 in a 64-bit reg
__device__ __forceinline__ ull h2f2(uint32_t u) {
    ull r;
    asm("{\n\t.reg .f16 lo, hi;\n\t.reg .f32 flo, fhi;\n\t"
        "mov.b32 {lo, hi}, %1;\n\t"
        "cvt.f32.f16 flo, lo;\n\t"
        "cvt.f32.f16 fhi, hi;\n\t"
        "mov.b64 %0, {flo, fhi};\n\t}" : "=l"(r) : "r"(u));
    return r;
}
// read one f16 scalar from the x tile as f32
__device__ __forceinline__ float xs_rd(const float* __restrict__ sm, int c, int p) {
    uint16_t h = ((const uint16_t*)sm)[(O_XS + c * RSXU) * 2 + p];
    float f;
    asm("{\n\t.reg .f16 hh;\n\tmov.b16 hh, %1;\n\tcvt.f32.f16 %0, hh;\n\t}" : "=f"(f) : "h"(h));
    return f;
}

// ---- async-stage one 64-k pass of weights: W[192 co][k0..k0+63] -> smem[co*68 + kc*4] ----
__device__ __forceinline__ void cp_stage(const float* __restrict__ W, int k0,
                                         uint32_t dstBase, int tid)
{
#pragma unroll
    for (int j = 0; j < 6; ++j) {
        int q = tid + j * 512;
        int co = q >> 4;
        int kc = q & 15;
        uint32_t dst = dstBase + (uint32_t)(co * RSW + kc * 4) * 4u;
        const float* src = W + co * 192 + k0 + kc * 4;
        asm volatile("cp.async.cg.shared.global [%0], [%1], 16;" :: "r"(dst), "l"(src));
    }
    asm volatile("cp.async.commit_group;" ::: "memory");
}

// one k-step: dup each of 6 weights to (w,w), 12 packed FFMA2 (24 MACs)
#define KSTEP(CMP, XA, XB) { \
    ull d; \
    d = pk2d(w0.CMP); accA[0] = ffma2(d, XA, accA[0]); accB[0] = ffma2(d, XB, accB[0]); \
    d = pk2d(w1.CMP); accA[1] = ffma2(d, XA, accA[1]); accB[1] = ffma2(d, XB, accB[1]); \
    d = pk2d(w2.CMP); accA[2] = ffma2(d, XA, accA[2]); accB[2] = ffma2(d, XB, accB[2]); \
    d = pk2d(w3.CMP); accA[3] = ffma2(d, XA, accA[3]); accB[3] = ffma2(d, XB, accB[3]); \
    d = pk2d(w4.CMP); accA[4] = ffma2(d, XA, accA[4]); accB[4] = ffma2(d, XB, accB[4]); \
    d = pk2d(w5.CMP); accA[5] = ffma2(d, XA, accA[5]); accB[5] = ffma2(d, XB, accB[5]); \
}

// 192x64 GEMM, K=192: out[co][p] = bias[co] + sum_k W[co][k] * in_f16[k][p]
// 3 K-passes of 64, weights (fp32) double-buffered via cp.async; x operand f16.
// Thread tile: 6 co x 4 p (f32x2 pairs).
template <bool TO_SMEM>
__device__ __forceinline__ void gemm_big(const float* __restrict__ W, const float* __restrict__ bias,
                                         float* __restrict__ gout,
                                         float* __restrict__ sm, uint32_t sb, int tid)
{
    const int warp = tid >> 5, lane = tid & 31;
    const int p = ((warp >> 2) * 4 + (lane & 3)) * 4;       // 16 p-quads
    const int col = ((warp & 3) * 8 + (lane >> 2)) * 6;     // 0..186

    ull accA[6], accB[6];
#pragma unroll
    for (int i = 0; i < 6; ++i) {
        float bi = bias[col + i];
        accA[i] = pk2(bi, bi);
        accB[i] = pk2(bi, bi);
    }
    // byte address of the thread's 4 f16 p-values in row 0
    const uint32_t xbase = sb + (uint32_t)O_XS * 4u + (uint32_t)p * 2u;

#pragma unroll 1
    for (int pass = 0; pass < 3; ++pass) {
        if (pass < 2) {
            cp_stage(W, (pass + 1) * 64, sb + (uint32_t)(O_WT + (pass & 1) * WBUF) * 4u, tid);
            asm volatile("cp.async.wait_group 1;" ::: "memory");
        } else {
            asm volatile("cp.async.wait_group 0;" ::: "memory");
        }
        __syncthreads();
        const int wb = O_WT + ((pass + 1) & 1) * WBUF;
        const int kb = pass * 64;
#pragma unroll 2
        for (int k4 = 0; k4 < 16; ++k4) {
            float4 w0 = *(const float4*)&sm[wb + (col + 0) * RSW + k4 * 4];
            float4 w1 = *(const float4*)&sm[wb + (col + 1) * RSW + k4 * 4];
            float4 w2 = *(const float4*)&sm[wb + (col + 2) * RSW + k4 * 4];
            float4 w3 = *(const float4*)&sm[wb + (col + 3) * RSW + k4 * 4];
            float4 w4 = *(const float4*)&sm[wb + (col + 4) * RSW + k4 * 4];
            float4 w5 = *(const float4*)&sm[wb + (col + 5) * RSW + k4 * 4];
            uint32_t u0, u1, u2, u3, u4, u5, u6, u7;
            {
                uint32_t a0 = xbase + (uint32_t)((kb + k4 * 4 + 0) * (RSXU * 4));
                uint32_t a1 = xbase + (uint32_t)((kb + k4 * 4 + 1) * (RSXU * 4));
                uint32_t a2 = xbase + (uint32_t)((kb + k4 * 4 + 2) * (RSXU * 4));
                uint32_t a3 = xbase + (uint32_t)((kb + k4 * 4 + 3) * (RSXU * 4));
                asm("ld.shared.v2.u32 {%0,%1}, [%2];" : "=r"(u0), "=r"(u1) : "r"(a0));
                asm("ld.shared.v2.u32 {%0,%1}, [%2];" : "=r"(u2), "=r"(u3) : "r"(a1));
                asm("ld.shared.v2.u32 {%0,%1}, [%2];" : "=r"(u4), "=r"(u5) : "r"(a2));
                asm("ld.shared.v2.u32 {%0,%1}, [%2];" : "=r"(u6), "=r"(u7) : "r"(a3));
            }
            { ull xA = h2f2(u0), xB = h2f2(u1); KSTEP(x, xA, xB); }
            { ull xA = h2f2(u2), xB = h2f2(u3); KSTEP(y, xA, xB); }
            { ull xA = h2f2(u4), xB = h2f2(u5); KSTEP(z, xA, xB); }
            { ull xA = h2f2(u6), xB = h2f2(u7); KSTEP(w, xA, xB); }
        }
        __syncthreads();   // buffer free for the next pass's cp.async
    }

#pragma unroll
    for (int i = 0; i < 6; ++i) {
        float4 v;
        unpk2(v.x, v.y, accA[i]);
        unpk2(v.z, v.w, accB[i]);
        if (TO_SMEM) *(float4*)&sm[O_QS + (col + i) * RSQ + p] = v;
        else         *(float4*)&gout[(col + i) * 64 + p] = v;
    }
    __syncthreads();
}

__global__ void __launch_bounds__(TPB, 1)
dat_fused_kernel(const float* __restrict__ x,
                 const float* __restrict__ wq, const float* __restrict__ bq,
                 const float* __restrict__ wk, const float* __restrict__ bk,
                 const float* __restrict__ wv, const float* __restrict__ bv,
                 const float* __restrict__ wo, const float* __restrict__ bo,
                 const float* __restrict__ dww, const float* __restrict__ dwb,
                 const float* __restrict__ lng, const float* __restrict__ lnb,
                 const float* __restrict__ pww, const float* __restrict__ rpe,
                 float* __restrict__ out, int writePR)
{
    extern __shared__ float sm[];
    const int b = blockIdx.x;
    const int tid = threadIdx.x;
    const uint32_t sb = (uint32_t)__cvta_generic_to_shared(sm);

    // async-prefetch q-proj weight pass 0 into buffer 1 (overlaps x staging)
    cp_stage(wq, 0, sb + (uint32_t)(O_WT + WBUF) * 4u, tid);

    // ---- stage x (transpose + round to f16 pairs) and persistent params ----
    const float* xb = x + (size_t)b * (NPOS * CDIM);
    for (int t = tid; t < CDIM * 32; t += TPB) {
        int pp = t / CDIM;            // p-pair 0..31
        int c = t - pp * CDIM;
        float v0 = xb[(2 * pp) * CDIM + c];
        float v1 = xb[(2 * pp + 1) * CDIM + c];
        uint32_t u;
        asm("cvt.rn.f16x2.f32 %0, %1, %2;" : "=r"(u) : "f"(v1), "f"(v0));
        ((uint32_t*)sm)[O_XS + c * RSXU + pp] = u;
    }
    for (int t = tid; t < 1350; t += TPB) sm[O_RPE + t] = rpe[t];
    for (int t = tid; t < 576; t += TPB) sm[O_DWW + t] = dww[t];
    if (tid < 64) {
        sm[O_DWB + tid] = dwb[tid];
        sm[O_LNG + tid] = lng[tid];
        sm[O_LNB + tid] = lnb[tid];
    }
    if (tid >= 64 && tid < 192) sm[O_PWW + tid - 64] = pww[tid - 64];
    __syncthreads();

    // ---- q = Wq x + bq ----
    gemm_big<true>(wq, bq, nullptr, sm, sb, tid);

    // ---- offset network: 48 items (group g, sample s), 3 per warp ----
    const int warp = tid >> 5, lane = tid & 31;
    for (int kk = 0; kk < 3; ++kk) {
        const int item = warp * 3 + kk;
        const int g = item >> 4;
        const int s = item & 15;
        const int si = s >> 2, sj = s & 3;
        const int ch0 = lane, ch1 = lane + 32;
        float v0 = sm[O_DWB + ch0];
        float v1 = sm[O_DWB + ch1];
        const int iy0 = 2 * si - 1, ix0 = 2 * sj - 1;
#pragma unroll
        for (int di = 0; di < 3; ++di) {
            int iy = iy0 + di;
            if (iy < 0 || iy > 7) continue;
#pragma unroll
            for (int dj = 0; dj < 3; ++dj) {
                int ix = ix0 + dj;
                if (ix < 0 || ix > 7) continue;
                float q0 = sm[O_QS + (g * 64 + ch0) * RSQ + iy * 8 + ix];
                float q1 = sm[O_QS + (g * 64 + ch1) * RSQ + iy * 8 + ix];
                v0 += sm[O_DWW + ch0 * 9 + di * 3 + dj] * q0;
                v1 += sm[O_DWW + ch1 * 9 + di * 3 + dj] * q1;
            }
        }
        float ssum = v0 + v1, ssq = v0 * v0 + v1 * v1;
#pragma unroll
        for (int o = 16; o > 0; o >>= 1) {
            ssum += __shfl_xor_sync(0xffffffffu, ssum, o);
            ssq += __shfl_xor_sync(0xffffffffu, ssq, o);
        }
        float mu = ssum * (1.0f / 64.0f);
        float var = ssq * (1.0f / 64.0f) - mu * mu;
        float rstd = rsqrtf(var + 1e-5f);
        v0 = (v0 - mu) * rstd * sm[O_LNG + ch0] + sm[O_LNB + ch0];
        v1 = (v1 - mu) * rstd * sm[O_LNG + ch1] + sm[O_LNB + ch1];
        v0 = 0.5f * v0 * (1.0f + erff(v0 * 0.70710678118654752f));
        v1 = 0.5f * v1 * (1.0f + erff(v1 * 0.70710678118654752f));
        float o0 = sm[O_PWW + ch0] * v0 + sm[O_PWW + ch1] * v1;
        float o1 = sm[O_PWW + 64 + ch0] * v0 + sm[O_PWW + 64 + ch1] * v1;
#pragma unroll
        for (int o = 16; o > 0; o >>= 1) {
            o0 += __shfl_xor_sync(0xffffffffu, o0, o);
            o1 += __shfl_xor_sync(0xffffffffu, o1, o);
        }
        if (lane == 0) {
            float offy = tanhf(o0) * (2.0f / 3.0f);
            float offx = tanhf(o1) * (2.0f / 3.0f);
            float ry = (2 * si - 3) * 0.25f;
            float rx = (2 * sj - 3) * 0.25f;
            float py = offy + ry;
            float px = offx + rx;
            sm[O_POS + item * 2 + 0] = py;
            sm[O_POS + item * 2 + 1] = px;
            float gx = (px + 1.0f) * 3.5f;
            float gy = (py + 1.0f) * 3.5f;
            float x0f = floorf(gx), y0f = floorf(gy);
            int jx0 = (int)x0f, jy0 = (int)y0f;
            float wx1 = gx - x0f, wy1 = gy - y0f;
            float wxs[2] = {1.0f - wx1, wx1};
            float wys[2] = {1.0f - wy1, wy1};
            int* smpI = (int*)sm;
#pragma unroll
            for (int n = 0; n < 4; ++n) {
                int xi = jx0 + (n & 1);
                int yi = jy0 + (n >> 1);
                bool val = (xi >= 0 && xi <= 7 && yi >= 0 && yi <= 7);
                sm[O_SMPW + item * 4 + n] = val ? wxs[n & 1] * wys[n >> 1] : 0.0f;
                smpI[O_SMPI + item * 4 + n] = val ? (yi * 8 + xi) : 0;
            }
            if (writePR) {
                size_t po = ((size_t)b * 48 + item) * 2;
                out[POS_OFF + po + 0] = py;
                out[POS_OFF + po + 1] = px;
                out[REF_OFF + po + 0] = ry;
                out[REF_OFF + po + 1] = rx;
            }
        }
    }
    __syncthreads();

    // ---- bilinear sample x (f16) at pos -> samp[c][s] (f32) ----
    for (int t = tid; t < CDIM * NS; t += TPB) {
        int c = t >> 4;
        int s = t & 15;
        int item = (c >> 6) * 16 + s;
        const float* wp = &sm[O_SMPW + item * 4];
        const int* ip = ((const int*)sm) + O_SMPI + item * 4;
        sm[O_SAMP + c * RSS + s] =
            wp[0] * xs_rd(sm, c, ip[0]) + wp[1] * xs_rd(sm, c, ip[1])
          + wp[2] * xs_rd(sm, c, ip[2]) + wp[3] * xs_rd(sm, c, ip[3]);
    }
    __syncthreads();

    // ---- k, v projections: weights direct from L2, thread = (co, 8 s-cols) ----
    if (tid < 384) {
        const int co = tid >> 1;
        const int sh = (tid & 1) * 8;
        const float bkc = bk[co], bvc = bv[co];
        float4 ak0 = make_float4(bkc, bkc, bkc, bkc), ak1 = ak0;
        float4 av0 = make_float4(bvc, bvc, bvc, bvc), av1 = av0;
#pragma unroll 4
        for (int k4 = 0; k4 < 48; ++k4) {
            float4 wk4 = __ldg((const float4*)&wk[co * 192 + k4 * 4]);
            float4 wv4 = __ldg((const float4*)&wv[co * 192 + k4 * 4]);
#pragma unroll
            for (int j = 0; j < 4; ++j) {
                float wkj = (j == 0) ? wk4.x : (j == 1) ? wk4.y : (j == 2) ? wk4.z : wk4.w;
                float wvj = (j == 0) ? wv4.x : (j == 1) ? wv4.y : (j == 2) ? wv4.z : wv4.w;
                float4 s0 = *(const float4*)&sm[O_SAMP + (k4 * 4 + j) * RSS + sh];
                float4 s1 = *(const float4*)&sm[O_SAMP + (k4 * 4 + j) * RSS + sh + 4];
                ak0.x += wkj * s0.x; ak0.y += wkj * s0.y; ak0.z += wkj * s0.z; ak0.w += wkj * s0.w;
                ak1.x += wkj * s1.x; ak1.y += wkj * s1.y; ak1.z += wkj * s1.z; ak1.w += wkj * s1.w;
                av0.x += wvj * s0.x; av0.y += wvj * s0.y; av0.z += wvj * s0.z; av0.w += wvj * s0.w;
                av1.x += wvj * s1.x; av1.y += wvj * s1.y; av1.z += wvj * s1.z; av1.w += wvj * s1.w;
            }
        }
        *(float4*)&sm[O_KS + co * RSS + sh] = ak0;
        *(float4*)&sm[O_KS + co * RSS + sh + 4] = ak1;
        *(float4*)&sm[O_VS + co * RSS + sh] = av0;
        *(float4*)&sm[O_VS + co * RSS + sh + 4] = av1;
    }
    __syncthreads();

    // async-prefetch o-proj weight pass 0 into buffer 1 (upper half — does not
    // alias SAMP/KS/VS in buffer 0); attention below hides the latency.
    cp_stage(wo, 0, sb + (uint32_t)(O_WT + WBUF) * 4u, tid);

    // ---- attention: item = (head, query position), 384 items ----
    for (int it = tid; it < NHEAD * NPOS; it += TPB) {
        const int h = it >> 6;
        const int p = it & 63;
        const int g = h >> 1;
        float a[16];
#pragma unroll
        for (int s = 0; s < 16; ++s) a[s] = 0.0f;
#pragma unroll 4
        for (int c = 0; c < 32; ++c) {
            float qv = sm[O_QS + (h * 32 + c) * RSQ + p];
            const float4* kr = (const float4*)&sm[O_KS + (h * 32 + c) * RSS];
            float4 k0 = kr[0], k1 = kr[1], k2 = kr[2], k3 = kr[3];
            a[0] += qv * k0.x; a[1] += qv * k0.y; a[2] += qv * k0.z; a[3] += qv * k0.w;
            a[4] += qv * k1.x; a[5] += qv * k1.y; a[6] += qv * k1.z; a[7] += qv * k1.w;
            a[8] += qv * k2.x; a[9] += qv * k2.y; a[10] += qv * k2.z; a[11] += qv * k2.w;
            a[12] += qv * k3.x; a[13] += qv * k3.y; a[14] += qv * k3.z; a[15] += qv * k3.w;
        }
        const float scale = 0.17677669529663687f;
        float qy = (2 * (p >> 3) - 7) * 0.125f;
        float qx = (2 * (p & 7) - 7) * 0.125f;
        const float* rpeh = &sm[O_RPE + h * 225];
        float mx = -1e30f;
#pragma unroll
        for (int s = 0; s < 16; ++s) {
            float py = sm[O_POS + (g * 16 + s) * 2 + 0];
            float px = sm[O_POS + (g * 16 + s) * 2 + 1];
            float dy = (qy - py) * 0.5f;
            float dx = (qx - px) * 0.5f;
            float gx = (dx + 1.0f) * 7.0f;
            float gy = (dy + 1.0f) * 7.0f;
            float x0f = floorf(gx), y0f = floorf(gy);
            int jx0 = (int)x0f, jy0 = (int)y0f;
            float wx1 = gx - x0f, wy1 = gy - y0f;
            float bias = 0.0f;
            if (jx0 >= 0 && jx0 <= 14 && jy0 >= 0 && jy0 <= 14)
                bias += (1.0f - wx1) * (1.0f - wy1) * rpeh[jy0 * 15 + jx0];
            if (jx0 + 1 >= 0 && jx0 + 1 <= 14 && jy0 >= 0 && jy0 <= 14)
                bias += wx1 * (1.0f - wy1) * rpeh[jy0 * 15 + jx0 + 1];
            if (jx0 >= 0 && jx0 <= 14 && jy0 + 1 >= 0 && jy0 + 1 <= 14)
                bias += (1.0f - wx1) * wy1 * rpeh[(jy0 + 1) * 15 + jx0];
            if (jx0 + 1 >= 0 && jx0 + 1 <= 14 && jy0 + 1 >= 0 && jy0 + 1 <= 14)
                bias += wx1 * wy1 * rpeh[(jy0 + 1) * 15 + jx0 + 1];
            a[s] = a[s] * scale + bias;
            mx = fmaxf(mx, a[s]);
        }
        float ssum = 0.0f;
#pragma unroll
        for (int s = 0; s < 16; ++s) { a[s] = __expf(a[s] - mx); ssum += a[s]; }
        float inv = 1.0f / ssum;
#pragma unroll
        for (int s = 0; s < 16; ++s) a[s] *= inv;
#pragma unroll 4
        for (int cl = 0; cl < 32; ++cl) {
            int c = h * 32 + cl;
            const float4* vr = (const float4*)&sm[O_VS + c * RSS];
            float4 v0 = vr[0], v1 = vr[1], v2 = vr[2], v3 = vr[3];
            float acc = a[0]*v0.x + a[1]*v0.y + a[2]*v0.z + a[3]*v0.w
                      + a[4]*v1.x + a[5]*v1.y + a[6]*v1.z + a[7]*v1.w
                      + a[8]*v2.x + a[9]*v2.y + a[10]*v2.z + a[11]*v2.w
                      + a[12]*v3.x + a[13]*v3.y + a[14]*v3.z + a[15]*v3.w;
            // store attn-out as f16 into the XS tile (x is dead)
            uint16_t h16;
            asm("cvt.rn.f16.f32 %0, %1;" : "=h"(h16) : "f"(acc));
            ((uint16_t*)sm)[c * (RSXU * 2) + p] = h16;
        }
    }
    __syncthreads();

    // ---- y = Wo attn_out + bo (direct to gmem) ----
    gemm_big<false>(wo, bo, out + (size_t)b * (CDIM * NPOS), sm, sb, tid);
}

extern "C" void kernel_launch(void* const* d_in, const int* in_sizes, int n_in,
                              void* d_out, int out_size)
{
    (void)in_sizes; (void)n_in;
    const float* x   = (const float*)d_in[0];
    const float* wq  = (const float*)d_in[1];
    const float* bq  = (const float*)d_in[2];
    const float* wk  = (const float*)d_in[3];
    const float* bk  = (const float*)d_in[4];
    const float* wv  = (const float*)d_in[5];
    const float* bv  = (const float*)d_in[6];
    const float* wo  = (const float*)d_in[7];
    const float* bo  = (const float*)d_in[8];
    const float* dww = (const float*)d_in[9];
    const float* dwb = (const float*)d_in[10];
    const float* lng = (const float*)d_in[11];
    const float* lnb = (const float*)d_in[12];
    const float* pww = (const float*)d_in[13];
    const float* rpe = (const float*)d_in[14];
    float* out = (float*)d_out;

    int writePR = (out_size >= (REF_OFF + PR_SIZE)) ? 1 : 0;

    cudaFuncSetAttribute(dat_fused_kernel,
                         cudaFuncAttributeMaxDynamicSharedMemorySize, SMEM_BYTES);
    dat_fused_kernel<<<NBATCH, TPB, SMEM_BYTES>>>(
        x, wq, bq, wk, bk, wv, bv, wo, bo, dww, dwb, lng, lnb, pww, rpe, out, writePR);
}